// round 17
// baseline (speedup 1.0000x reference)
#include <cuda_runtime.h>
#include <cuda_bf16.h>
#include <math.h>
#include <stdint.h>

// ---------------- problem constants ----------------
#define B_  8
#define T_  4096
#define D_  256
#define M_  (B_ * T_)      // 32768
#define K_  256
#define N_TOT 512

// ---------------- scan chunking ----------------
#define LCH 64
#define NCH (T_ / LCH)          // 64 chunks per batch
#define NBLK ((M_ / LCH) * 2)   // 1024 fused blocks (2 d-halves)

// ---------------- scratch (static device allocations) ----------------
__device__ uint4 g_Whi4[(N_TOT * K_) / 8];       // permuted rows (see prep)
__device__ uint4 g_Wlo4[(N_TOT * K_) / 8];
__device__ uint4 g_Ahi4[((size_t)M_ * K_) / 8];  // [m][k] bf16 hi
__device__ uint4 g_Alo4[((size_t)M_ * K_) / 8];  // [m][k] bf16 lo
// decoupled-lookback state: NBLK * 128 channels = 131072 slots
__device__ float    g_SA [NBLK * 128];
__device__ float    g_SHl[NBLK * 128];
__device__ float    g_SHI[NBLK * 128];
__device__ uint32_t g_flag[NBLK * 128];

// ---------------- smem layout ----------------
// stage: Ahi 8K | Alo 8K | Whi 32K | Wlo 32K = 80K; two stages = 160K
#define ST_ALO   8192
#define ST_WHI   16384
#define ST_WLO   49152
#define ST_SIZE  81920
#define SM_BIAS  163840     // 256 floats
#define SM_MK    164864     // 64 floats
#define SM_TOTAL 165120
// epilogue staging (reuses stage-0 space after final sync)
#define SM_XS    0          // xs[64][STG]
#define SM_FS    34816      // fs[64][STG]
#define STG      132

// ---------------- asm helpers (base sm_103 features only) ----------------
__device__ __forceinline__ uint32_t smem_u32(const void* p) {
    uint32_t a;
    asm("{ .reg .u64 t; cvta.to.shared.u64 t, %1; cvt.u32.u64 %0, t; }" : "=r"(a) : "l"(p));
    return a;
}
#define LDSM4(r, addr) asm volatile( \
    "ldmatrix.sync.aligned.m8n8.x4.shared.b16 {%0,%1,%2,%3}, [%4];" \
    : "=r"((r)[0]), "=r"((r)[1]), "=r"((r)[2]), "=r"((r)[3]) : "r"(addr))
#define MMA(d, a, b0v, b1v) asm volatile( \
    "mma.sync.aligned.m16n8k16.row.col.f32.bf16.bf16.f32 " \
    "{%0,%1,%2,%3}, {%4,%5,%6,%7}, {%8,%9}, {%0,%1,%2,%3};" \
    : "+f"((d)[0]), "+f"((d)[1]), "+f"((d)[2]), "+f"((d)[3]) \
    : "r"((a)[0]), "r"((a)[1]), "r"((a)[2]), "r"((a)[3]), "r"(b0v), "r"(b1v))
__device__ __forceinline__ void cp_async16(uint32_t dst, const void* src) {
    asm volatile("cp.async.cg.shared.global [%0], [%1], 16;" :: "r"(dst), "l"(src));
}
#define CP_COMMIT() asm volatile("cp.async.commit_group;" ::: "memory")
__device__ __forceinline__ void st_release_u32(uint32_t* p, uint32_t v) {
    asm volatile("st.global.release.gpu.b32 [%0], %1;" :: "l"(p), "r"(v) : "memory");
}
__device__ __forceinline__ uint32_t ld_acquire_u32(const uint32_t* p) {
    uint32_t v;
    asm volatile("ld.global.acquire.gpu.b32 %0, [%1];" : "=r"(v) : "l"(p) : "memory");
    return v;
}

// ---------------------------------------------------------------------------
// prep: A fp32 -> hi/lo bf16 (all threads); W split + flag zero.
// W permuted rows: p = hb*256 + branch*128 + (d & 127), hb = d >> 7.
// ---------------------------------------------------------------------------
__global__ void prep_kernel(const float4* __restrict__ A4,
                            const float* __restrict__ W_in,
                            const float* __restrict__ W_f)
{
    int i = blockIdx.x * blockDim.x + threadIdx.x;   // 0 .. 2,097,151
    float4 a = A4[i];
    __nv_bfloat16 h0 = __float2bfloat16_rn(a.x), h1 = __float2bfloat16_rn(a.y),
                  h2 = __float2bfloat16_rn(a.z), h3 = __float2bfloat16_rn(a.w);
    __nv_bfloat162 hp0 = {h0, h1}, hp1 = {h2, h3};
    __nv_bfloat162 lp0 = __floats2bfloat162_rn(a.x - __bfloat162float(h0),
                                               a.y - __bfloat162float(h1));
    __nv_bfloat162 lp1 = __floats2bfloat162_rn(a.z - __bfloat162float(h2),
                                               a.w - __bfloat162float(h3));
    ((uint2*)g_Ahi4)[i] = make_uint2(*(uint32_t*)&hp0, *(uint32_t*)&hp1);
    ((uint2*)g_Alo4)[i] = make_uint2(*(uint32_t*)&lp0, *(uint32_t*)&lp1);

    if (i < NBLK * 128) {            // == N_TOT*K_ == 131072
        g_flag[i] = 0u;
        int p = i >> 8, k = i & 255;
        int hb = p >> 8;
        int rem = p & 255;
        int branch = rem >> 7;
        int d = hb * 128 + (rem & 127);
        float v = branch ? W_f[d * K_ + k] : W_in[d * K_ + k];
        __nv_bfloat16 hi = __float2bfloat16_rn(v);
        ((__nv_bfloat16*)g_Whi4)[i] = hi;
        ((__nv_bfloat16*)g_Wlo4)[i] = __float2bfloat16_rn(v - __bfloat162float(hi));
    }
}

// ---------------------------------------------------------------------------
// Fused: split-bf16 mma GEMM (register-pipelined fragments) + activations +
// decoupled-lookback scan + output.
// grid = 1024 (512 m-chunks x 2 d-halves), 512 threads, 1 CTA/SM.
// Block tile: 64 m x 256 n. 16 warps (2 x 8), each 32 m x 32 n.
// ---------------------------------------------------------------------------
__global__ __launch_bounds__(512, 1)
void fused_kernel(const float* __restrict__ b_in,
                  const float* __restrict__ b_f,
                  const float* __restrict__ mask,
                  float* __restrict__ out)
{
    extern __shared__ __align__(16) char smem[];
    const uint32_t sb = smem_u32(smem);
    const int tid = threadIdx.x;
    const int w   = tid >> 5, l = tid & 31;
    const int wm  = w >> 3;           // 0..1, 32-row strip
    const int wn  = w & 7;            // 0..7, 32-col strip
    const int bid = blockIdx.x;
    const int m0  = (bid >> 1) * 64;
    const int hb  = bid & 1;          // d-half

    // issue one stage = A chunk (hi+lo) + W chunk (hi+lo) for k-chunk kc
    auto issueStage = [&](int kc, int buf) {
        const uint32_t base = sb + (buf ? ST_SIZE : 0);
        // A: 64 rows x 8 u4 x 2 arrays = 1024 -> 2 per thread
#pragma unroll
        for (int it = 0; it < 2; it++) {
            int v   = it * 512 + tid;
            int arr = v >> 9;
            int u   = v & 511;
            int row = u >> 3, c8 = u & 7;
            uint32_t dst = base + (arr ? ST_ALO : 0)
                         + row * 128 + ((c8 ^ (row & 7)) << 4);
            const uint4* src = (arr ? g_Alo4 : g_Ahi4)
                             + ((size_t)(m0 + row) * 32 + kc * 8 + c8);
            cp_async16(dst, src);
        }
        // W: 256 rows x 8 u4 x 2 arrays = 4096 -> 8 per thread
#pragma unroll
        for (int it = 0; it < 8; it++) {
            int v   = it * 512 + tid;
            int arr = v >> 11;
            int u   = v & 2047;
            int n   = u >> 3, k8 = u & 7;
            uint32_t dst = base + (arr ? ST_WLO : ST_WHI)
                         + n * 128 + ((k8 ^ (n & 7)) << 4);
            const uint4* src = (arr ? g_Wlo4 : g_Whi4)
                             + ((size_t)(hb * 256 + n) * 32 + kc * 8 + k8);
            cp_async16(dst, src);
        }
        CP_COMMIT();
    };

    issueStage(0, 0);
    issueStage(1, 1);

    // bias / mask staging
    if (tid < 256) {
        int branch = tid >> 7;
        int d = hb * 128 + (tid & 127);
        *(float*)(smem + SM_BIAS + tid * 4) = branch ? b_f[d] : b_in[d];
    }
    if (tid >= 256 && tid < 320) {
        int r = tid - 256;
        *(float*)(smem + SM_MK + r * 4) = mask[m0 + r] * 10000.0f;
    }

    float acc[2][4][4];
#pragma unroll
    for (int a1 = 0; a1 < 2; a1++)
#pragma unroll
        for (int a2 = 0; a2 < 4; a2++)
#pragma unroll
            for (int a3 = 0; a3 < 4; a3++) acc[a1][a2][a3] = 0.0f;

    const int g = l >> 3;
    // warp-constant pieces of fragment addresses
    const int r0 = wm * 32 + ((g & 1) << 3) + (l & 7);                 // A row
    const int cbase = (g & 2) << 2;                                    // A col sub
    const int n0 = wn * 32 + ((g & 2) << 2) + (l & 7);                 // W row (ng=0)
    const int kbase = (g & 1) << 3;                                    // W col sub

    // double-buffered fragments: [fb][strip]
    uint32_t ah[2][2][4], al[2][2][4], bh[2][2][4], bl[2][2][4];

    auto ldfrag = [&](uint32_t base, int ks, int fb) {
        int c = ks * 16 + cbase;
        uint32_t aoff = r0 * 128 + ((((c >> 3) ^ (r0 & 7))) << 4);
        LDSM4(ah[fb][0], base + aoff);
        LDSM4(ah[fb][1], base + aoff + 2048);           // +16 rows
        LDSM4(al[fb][0], base + ST_ALO + aoff);
        LDSM4(al[fb][1], base + ST_ALO + aoff + 2048);
        int kk = ks * 16 + kbase;
        uint32_t sw = (((kk >> 3) ^ (n0 & 7)) << 4);
        uint32_t w0 = n0 * 128 + sw;
        uint32_t w1 = (n0 + 16) * 128 + ((((kk >> 3) ^ ((n0 + 16) & 7))) << 4);
        LDSM4(bh[fb][0], base + ST_WHI + w0);
        LDSM4(bh[fb][1], base + ST_WHI + w1);
        LDSM4(bl[fb][0], base + ST_WLO + w0);
        LDSM4(bl[fb][1], base + ST_WLO + w1);
    };

    for (int kc = 0; kc < 4; kc++) {
        const int buf = kc & 1;
        if (kc < 3) asm volatile("cp.async.wait_group 1;" ::: "memory");
        else        asm volatile("cp.async.wait_group 0;" ::: "memory");
        __syncthreads();
        const uint32_t base = sb + (buf ? ST_SIZE : 0);

        ldfrag(base, 0, 0);
#pragma unroll
        for (int ks = 0; ks < 4; ks++) {
            const int fb = ks & 1;
            if (ks < 3) ldfrag(base, ks + 1, fb ^ 1);   // prefetch next fragments
            // 24 MMAs on buffered fragments (independent of the LDSMs above)
#pragma unroll
            for (int mt = 0; mt < 2; mt++)
#pragma unroll
                for (int ng = 0; ng < 2; ng++) {
                    MMA(acc[mt][ng * 2 + 0], ah[fb][mt], bh[fb][ng][0], bh[fb][ng][1]);
                    MMA(acc[mt][ng * 2 + 1], ah[fb][mt], bh[fb][ng][2], bh[fb][ng][3]);
                }
#pragma unroll
            for (int mt = 0; mt < 2; mt++)
#pragma unroll
                for (int ng = 0; ng < 2; ng++) {
                    MMA(acc[mt][ng * 2 + 0], al[fb][mt], bh[fb][ng][0], bh[fb][ng][1]);
                    MMA(acc[mt][ng * 2 + 1], al[fb][mt], bh[fb][ng][2], bh[fb][ng][3]);
                }
#pragma unroll
            for (int mt = 0; mt < 2; mt++)
#pragma unroll
                for (int ng = 0; ng < 2; ng++) {
                    MMA(acc[mt][ng * 2 + 0], ah[fb][mt], bl[fb][ng][0], bl[fb][ng][1]);
                    MMA(acc[mt][ng * 2 + 1], ah[fb][mt], bl[fb][ng][2], bl[fb][ng][3]);
                }
        }
        __syncthreads();
        if (kc < 2) issueStage(kc + 2, buf);
    }

    // -------- epilogue: activations -> smem staging --------
    float* xs = (float*)(smem + SM_XS);
    float* fs = (float*)(smem + SM_FS);
    const float* biasS = (const float*)(smem + SM_BIAS);
    const float* mkS   = (const float*)(smem + SM_MK);

#pragma unroll
    for (int mt = 0; mt < 2; mt++)
#pragma unroll
        for (int nt = 0; nt < 4; nt++) {
            int r = wm * 32 + mt * 16 + (l >> 2);
            int nl = wn * 32 + nt * 8 + 2 * (l & 3);
            bool isF = (nl >= 128);
            float* stg = isF ? fs : xs;
            int cc = nl & 127;
            float b0 = biasS[nl], b1 = biasS[nl + 1];
#pragma unroll
            for (int h = 0; h < 2; h++) {
                int rr = r + h * 8;
                float z0 = acc[mt][nt][h * 2 + 0] + b0;
                float z1 = acc[mt][nt][h * 2 + 1] + b1;
                float v0, v1;
                if (isF) {
                    float mk = mkS[rr];
                    z0 += mk; z1 += mk;
                    v0 = 1.0f / (1.0f + expf(-z0));
                    v1 = 1.0f / (1.0f + expf(-z1));
                } else {
                    v0 = tanhf(z0);
                    v1 = tanhf(z1);
                }
                stg[rr * STG + cc]     = v0;
                stg[rr * STG + cc + 1] = v1;
            }
        }
    __syncthreads();

    // -------- lookback scan: 128 threads, one per local channel --------
    if (tid < 128) {
        const int dl = tid;
        const int slot = bid * 128 + dl;

        float hl = 0.0f, Aa = 1.0f;
#pragma unroll 8
        for (int t = 0; t < LCH; t++) {
            float f = fs[t * STG + dl];
            float x = xs[t * STG + dl];
            float om = 1.0f - f;
            hl = fmaf(f, x, om * hl);
            Aa *= om;
        }

        const int c = (bid >> 1) & (NCH - 1);   // chunk index within batch
        float h0 = 0.0f;
        if (c != 0) {
            g_SA [slot] = Aa;
            g_SHl[slot] = hl;
            st_release_u32(&g_flag[slot], 1u);
            float mult = 1.0f;
            int p = slot - 256;                 // (bid-2)*128 + dl
            while (true) {
                uint32_t f;
                do { f = ld_acquire_u32(&g_flag[p]); } while (f == 0u);
                if (f == 2u) { h0 = fmaf(mult, g_SHI[p], h0); break; }
                h0 = fmaf(mult, g_SHl[p], h0);
                mult *= g_SA[p];
                p -= 256;
            }
        }
        g_SHI[slot] = fmaf(Aa, h0, hl);
        st_release_u32(&g_flag[slot], 2u);

        float h = h0;
        float* op = out + (size_t)m0 * D_ + hb * 128 + dl;
#pragma unroll 8
        for (int t = 0; t < LCH; t++) {
            float f = fs[t * STG + dl];
            float x = xs[t * STG + dl];
            h = fmaf(f, x - h, h);
            op[(size_t)t * D_] = h;
        }
    }
}

extern "C" void kernel_launch(void* const* d_in, const int* in_sizes, int n_in,
                              void* d_out, int out_size)
{
    const float* inputs = (const float*)d_in[0];
    const float* mask   = (const float*)d_in[1];
    const float* W_in   = (const float*)d_in[2];
    const float* b_in   = (const float*)d_in[3];
    const float* W_f    = (const float*)d_in[4];
    const float* b_f    = (const float*)d_in[5];
    float* out = (float*)d_out;

    cudaFuncSetAttribute(fused_kernel, cudaFuncAttributeMaxDynamicSharedMemorySize, SM_TOTAL);

    prep_kernel<<<(M_ * K_ / 4) / 256, 256>>>((const float4*)inputs, W_in, W_f);
    fused_kernel<<<NBLK, 512, SM_TOTAL>>>(b_in, b_f, mask, out);
}